// round 4
// baseline (speedup 1.0000x reference)
#include <cuda_runtime.h>
#include <math.h>

#define W 1024
#define H 1024
#define NB 4
#define NPIX (NB * W * H)

#define NPASS 10
#define RT 64                       // hysteresis rows per tile
#define HBLOCKS (NB * H / RT)       // 64 blocks
#define WPR 16                      // u64 words per row (1024 bits)

typedef unsigned long long u64;

// ---------------- device scratch (no runtime allocation) ----------------
__device__ u64 g_fill[NB * H * WPR];    // weak-or-strong bits
__device__ u64 g_strong[NB * H * WPR];  // strong bits (grows monotonically)
__device__ int g_changed[NPASS];

__constant__ int c_dy[8] = {0, -1, -1, -1, 0, 1, 1, 1};
__constant__ int c_dx[8] = {1,  1,  0, -1, -1, -1, 0, 1};

__device__ __forceinline__ int reflect1024(int t) {
    t = (t < 0) ? -t : t;
    return (t > 1023) ? (2046 - t) : t;
}
__device__ __forceinline__ int clamp1024(int t) {
    return (t < 0) ? 0 : ((t > 1023) ? 1023 : t);
}

// In-word bidirectional flood of seeds through runs of F.
// Returns ns with seed ⊆ ns ⊆ (bits of F connected-in-word to a seed).
__device__ __forceinline__ u64 wflood(u64 F, u64 seed) {
    u64 t = seed & F;
    u64 up = (((F + t) ^ F) & F) | t;          // toward MSB (may be partial; OK)
    u64 Fr = __brevll(F), sr = __brevll(up);
    u64 tr = sr & Fr;
    u64 dn = (((Fr + tr) ^ Fr) & Fr) | tr;     // toward LSB of original
    return __brevll(dn);
}

// =====================================================================
// Kernel A: gray -> 5x5 gaussian (direct, row-major FMA) -> sobel ->
//           magnitude -> NMS -> double threshold (emitted as bit planes).
//           32x32 tile, halo 4. Arithmetic identical to R2/R3.
// =====================================================================
__global__ __launch_bounds__(256) void canny_main(const float* __restrict__ in,
                                                  float* __restrict__ magout)
{
    __shared__ float4 SgQ[40][11];   // gray, pitch 44 floats (16B aligned rows)
    __shared__ float Sb[36][37];     // blurred at clamped (edge-pad) coords
    __shared__ float Smag[34][35];   // magnitude (0 outside image)
    __shared__ float Sgx[34][35];
    __shared__ float Sgy[34][35];
    float* Sg = (float*)SgQ;         // Sg[row*44 + col]

    const int tid = threadIdx.x;
    const int b  = blockIdx.z;
    const int y0 = blockIdx.y << 5;
    const int x0 = blockIdx.x << 5;
    const float* pr = in + (size_t)b * 3 * W * H;

    if (b == 0 && blockIdx.x == 0 && blockIdx.y == 0 && tid < NPASS)
        g_changed[tid] = 0;

    // gaussian weights exactly as numpy builds them (f32 throughout)
    const float E0 = 0.13533528323661270231f;   // exp(-2) correctly rounded
    const float E1 = 0.60653065971263342360f;   // exp(-0.5)
    const float gs = __fadd_rn(__fadd_rn(__fadd_rn(__fadd_rn(E0, E1), 1.0f), E1), E0);
    float g1d[5];
    g1d[0] = __fdiv_rn(E0, gs);
    g1d[1] = __fdiv_rn(E1, gs);
    g1d[2] = __fdiv_rn(1.0f, gs);
    g1d[3] = g1d[1];
    g1d[4] = g1d[0];
    float g2d[5][5];
#pragma unroll
    for (int r = 0; r < 5; ++r)
#pragma unroll
        for (int c = 0; c < 5; ++c)
            g2d[r][c] = __fmul_rn(g1d[r], g1d[c]);

    // ---- gray with reflect padding ----
    for (int k = tid; k < 40 * 40; k += 256) {
        int j = k / 40, i = k - j * 40;
        int ry = reflect1024(y0 - 4 + j);
        int rx = reflect1024(x0 - 4 + i);
        int o = ry * W + rx;
        float r = pr[o], g = pr[o + W * H], bl = pr[o + 2 * W * H];
        Sg[j * 44 + i] = __fadd_rn(__fadd_rn(__fmul_rn(0.299f, r), __fmul_rn(0.587f, g)),
                                   __fmul_rn(0.114f, bl));
    }
    __syncthreads();

    // ---- direct 5x5 gaussian at clamped (edge-pad) centers ----
    const bool interior = (blockIdx.x >= 1) && (blockIdx.x <= 30) &&
                          (blockIdx.y >= 1) && (blockIdx.y <= 30);
    if (interior) {
        for (int k = tid; k < 36 * 9; k += 256) {
            int j = k / 9, q = k - j * 9;           // output cols 4q..4q+3
            float acc0 = 0.f, acc1 = 0.f, acc2 = 0.f, acc3 = 0.f;
#pragma unroll
            for (int r = 0; r < 5; ++r) {
                float4 A = SgQ[j + r][q];
                float4 B = SgQ[j + r][q + 1];
                float v[8] = {A.x, A.y, A.z, A.w, B.x, B.y, B.z, B.w};
#pragma unroll
                for (int c = 0; c < 5; ++c) {
                    acc0 = fmaf(g2d[r][c], v[c],     acc0);
                    acc1 = fmaf(g2d[r][c], v[c + 1], acc1);
                    acc2 = fmaf(g2d[r][c], v[c + 2], acc2);
                    acc3 = fmaf(g2d[r][c], v[c + 3], acc3);
                }
            }
            Sb[j][4 * q + 0] = acc0;
            Sb[j][4 * q + 1] = acc1;
            Sb[j][4 * q + 2] = acc2;
            Sb[j][4 * q + 3] = acc3;
        }
    } else {
        for (int k = tid; k < 36 * 36; k += 256) {
            int j = k / 36, i = k - j * 36;
            int sj = clamp1024(y0 - 2 + j) - y0 + 4;   // center row in Sg, [2,37]
            int si = clamp1024(x0 - 2 + i) - x0 + 4;
            float acc = 0.0f;
#pragma unroll
            for (int r = 0; r < 5; ++r)
#pragma unroll
                for (int c = 0; c < 5; ++c)
                    acc = fmaf(g2d[r][c], Sg[(sj - 2 + r) * 44 + (si - 2 + c)], acc);
            Sb[j][i] = acc;
        }
    }
    __syncthreads();

    // ---- sobel + magnitude over [y0-1, y0+32] (zero outside image for NMS) ----
    for (int k = tid; k < 34 * 34; k += 256) {
        int j = k / 34, i = k - j * 34;
        float a00 = Sb[j][i],     a01 = Sb[j][i + 1],     a02 = Sb[j][i + 2];
        float a10 = Sb[j + 1][i],                         a12 = Sb[j + 1][i + 2];
        float a20 = Sb[j + 2][i], a21 = Sb[j + 2][i + 1], a22 = Sb[j + 2][i + 2];
        float gx = __fadd_rn(__fadd_rn(__fadd_rn(__fadd_rn(__fadd_rn(
                     -a00, a02), __fmul_rn(-2.0f, a10)), __fmul_rn(2.0f, a12)), -a20), a22);
        float gy = __fadd_rn(__fadd_rn(__fadd_rn(__fadd_rn(__fadd_rn(
                     -a00, __fmul_rn(-2.0f, a01)), -a02), a20), __fmul_rn(2.0f, a21)), a22);
        float s = __fadd_rn(__fadd_rn(__fmul_rn(gx, gx), __fmul_rn(gy, gy)), 1e-6f);
        float m = __fsqrt_rn(s);
        int yy = y0 - 1 + j, xx = x0 - 1 + i;
        bool inb = ((unsigned)yy < 1024u) && ((unsigned)xx < 1024u);
        Smag[j][i] = inb ? m : 0.0f;
        Sgx[j][i] = gx;
        Sgy[j][i] = gy;
    }
    __syncthreads();

    // ---- NMS + double threshold; emit magnitude + fill/strong bit planes ----
    unsigned* fillp   = (unsigned*)g_fill;
    unsigned* strongp = (unsigned*)g_strong;
    for (int k = tid; k < 1024; k += 256) {
        int j = k >> 5, i = k & 31;                 // i == lane, j uniform per warp
        float m  = Smag[j + 1][i + 1];
        float gx = Sgx[j + 1][i + 1];
        float gy = Sgy[j + 1][i + 1];
        float ang = __fmul_rn(atan2f(gy, gx), 57.29577951308232087680f);
        int q = (int)rintf(__fdiv_rn(ang, 45.0f));   // [-4,4], half-even
        int pos = q & 7;
        int neg = (q + 4) & 7;
        float np_ = Smag[j + 1 + c_dy[pos]][i + 1 + c_dx[pos]];
        float nn_ = Smag[j + 1 + c_dy[neg]][i + 1 + c_dx[neg]];
        float mo = (fminf(__fadd_rn(m, -np_), __fadd_rn(m, -nn_)) > 0.0f) ? m : 0.0f;
        int y = y0 + j;
        magout[(b * H + y) * W + x0 + i] = mo;
        unsigned fm = __ballot_sync(0xffffffffu, mo > 0.1f);
        unsigned sm = __ballot_sync(0xffffffffu, mo > 0.2f);
        if (i == 0) {
            int wi = (b * H + y) * (2 * WPR) + (x0 >> 5);
            fillp[wi] = fm;
            strongp[wi] = sm;
        }
    }
}

// =====================================================================
// Kernel B: one bit-parallel hysteresis pass, 64 rows x 1024 cols/block.
// Each thread owns a 4-row x 1-word column block in registers; sweeps
// alternate down/up (Gauss-Seidel), use in-word run flood, and run
// barrier-free in groups of 4 (monotone growth toward unique fixed
// point => relaxed races are benign and the result is deterministic).
// =====================================================================
#define P (WPR + 1)

__global__ __launch_bounds__(256) void hyst_pass(int pass)
{
    if (pass > 0 && g_changed[pass - 1] == 0) return;

    __shared__ u64 sSbuf[(RT + 2) * P];
    __shared__ u64 sFbuf[(RT + 2) * P];
    volatile u64* sS = sSbuf;
    const int tid = threadIdx.x;
    const int b  = blockIdx.x >> 4;
    const int y0 = (blockIdx.x & 15) * RT;

    // load halo tile (rows y0-1 .. y0+RT)
    for (int k = tid; k < (RT + 2) * WPR; k += 256) {
        int r = k >> 4, w = k & (WPR - 1);
        int gy = y0 + r - 1;
        u64 f = 0ull, s = 0ull;
        if ((unsigned)gy < (unsigned)H) {
            int o = (b * H + gy) * WPR + w;
            f = g_fill[o];
            s = g_strong[o];
        }
        sFbuf[r * P + w] = f;
        sSbuf[r * P + w] = s;
    }
    __syncthreads();

    // ownership: 4 consecutive rows x 1 word column per thread
    const int w  = tid & 15;
    const int r0 = ((tid >> 4) << 2) + 1;    // rows r0 .. r0+3 (1..64)
    u64 F[4], S[4];
#pragma unroll
    for (int i = 0; i < 4; ++i) {
        F[i] = sFbuf[(r0 + i) * P + w];
        S[i] = sSbuf[(r0 + i) * P + w];
    }

    int any = 0;
    int down = 1;
    for (;;) {
        int ch = 0;
#pragma unroll
        for (int sub = 0; sub < 4; ++sub) {
#pragma unroll
            for (int ii = 0; ii < 4; ++ii) {
                int i = down ? ii : (3 - ii);
                u64 Fi = F[i];
                u64 cur = S[i];
                if (Fi == cur) continue;
                int r = r0 + i;
                u64 above = (i > 0) ? S[i - 1] : sS[(r - 1) * P + w];
                u64 below = (i < 3) ? S[i + 1] : sS[(r + 1) * P + w];
                u64 X = above | cur | below;
                u64 XL = (w > 0)
                    ? (sS[(r - 1) * P + w - 1] | sS[r * P + w - 1] | sS[(r + 1) * P + w - 1])
                    : 0ull;
                u64 XR = (w < WPR - 1)
                    ? (sS[(r - 1) * P + w + 1] | sS[r * P + w + 1] | sS[(r + 1) * P + w + 1])
                    : 0ull;
                u64 d = X | (X << 1) | (XL >> 63) | (X >> 1) | (XR << 63);
                u64 ns = wflood(Fi, (Fi & d) | cur);
                if (ns != cur) {
                    S[i] = ns;
                    sS[r * P + w] = ns;
                    ch = 1;
                }
            }
            down ^= 1;
        }
        any |= ch;
        if (!__syncthreads_or(ch)) break;
    }

    if (__syncthreads_or(any)) {
#pragma unroll
        for (int i = 0; i < 4; ++i)
            g_strong[(b * H + y0 + r0 + i - 1) * WPR + w] = S[i];
        if (tid == 0) g_changed[pass] = 1;
    }
}

// =====================================================================
// Kernel C: edges = 1.0 where strong else 0.0
// =====================================================================
__global__ __launch_bounds__(256) void edges_final(float* __restrict__ e)
{
    int i = blockIdx.x * 256 + threadIdx.x;       // over NPIX/4
    unsigned wrd = ((const unsigned*)g_strong)[i >> 3];
    int sh = (i & 7) * 4;
    float4 f;
    f.x = (wrd >> (sh + 0)) & 1u ? 1.0f : 0.0f;
    f.y = (wrd >> (sh + 1)) & 1u ? 1.0f : 0.0f;
    f.z = (wrd >> (sh + 2)) & 1u ? 1.0f : 0.0f;
    f.w = (wrd >> (sh + 3)) & 1u ? 1.0f : 0.0f;
    ((float4*)e)[i] = f;
}

// =====================================================================
extern "C" void kernel_launch(void* const* d_in, const int* in_sizes, int n_in,
                              void* d_out, int out_size)
{
    (void)in_sizes; (void)n_in; (void)out_size;
    const float* x = (const float*)d_in[0];
    float* out = (float*)d_out;          // magnitude (4,1,1024,1024)
    float* edges = out + (size_t)NPIX;   // edges     (4,1,1024,1024)

    dim3 grid(32, 32, NB);
    canny_main<<<grid, 256>>>(x, out);

    for (int p = 0; p < NPASS; ++p)
        hyst_pass<<<HBLOCKS, 256>>>(p);

    edges_final<<<NPIX / 1024, 256>>>(edges);
}

// round 6
// speedup vs baseline: 1.0561x; 1.0561x over previous
#include <cuda_runtime.h>
#include <math.h>

#define W 1024
#define H 1024
#define NB 4
#define NPIX (NB * W * H)

#define NPASS 10
#define RT 64                       // hysteresis rows per tile
#define HBLOCKS (NB * H / RT)       // 64 blocks
#define WPR 16                      // u64 words per row (1024 bits)
#define P (WPR + 1)

typedef unsigned long long u64;

// ---------------- device scratch (no runtime allocation) ----------------
__device__ u64 g_fill[NB * H * WPR];    // weak-or-strong bits
__device__ u64 g_strong[NB * H * WPR];  // strong bits (grows monotonically)
__device__ int g_changed[NPASS];

__constant__ int c_dy[8] = {0, -1, -1, -1, 0, 1, 1, 1};
__constant__ int c_dx[8] = {1,  1,  0, -1, -1, -1, 0, 1};

__device__ __forceinline__ int reflect1024(int t) {
    t = (t < 0) ? -t : t;
    return (t > 1023) ? (2046 - t) : t;
}
__device__ __forceinline__ int clamp1024(int t) {
    return (t < 0) ? 0 : ((t > 1023) ? 1023 : t);
}

// In-word bidirectional flood of seeds through runs of F.
// Returns ns with seed ⊆ ns ⊆ (bits of F connected-in-word to a seed).
__device__ __forceinline__ u64 wflood(u64 F, u64 seed) {
    u64 t = seed & F;
    u64 up = (((F + t) ^ F) & F) | t;          // toward MSB
    u64 Fr = __brevll(F), sr = __brevll(up);
    u64 tr = sr & Fr;
    u64 dn = (((Fr + tr) ^ Fr) & Fr) | tr;     // toward LSB of original
    return __brevll(dn);
}

// =====================================================================
// Kernel A: gray -> 5x5 gaussian (direct, row-major FMA) -> sobel ->
//           magnitude -> NMS -> double threshold (bit planes out).
//           32x32 tile, halo 4. Arithmetic identical to R2/R3/R4.
// =====================================================================
__global__ __launch_bounds__(256) void canny_main(const float* __restrict__ in,
                                                  float* __restrict__ magout)
{
    __shared__ float4 SgQ[40][11];   // gray, pitch 44 floats
    __shared__ float Sb[36][37];
    __shared__ float Smag[34][35];
    __shared__ float Sgx[34][35];
    __shared__ float Sgy[34][35];
    float* Sg = (float*)SgQ;

    const int tid = threadIdx.x;
    const int b  = blockIdx.z;
    const int y0 = blockIdx.y << 5;
    const int x0 = blockIdx.x << 5;
    const float* pr = in + (size_t)b * 3 * W * H;

    if (b == 0 && blockIdx.x == 0 && blockIdx.y == 0 && tid < NPASS)
        g_changed[tid] = 0;

    const float E0 = 0.13533528323661270231f;   // exp(-2)
    const float E1 = 0.60653065971263342360f;   // exp(-0.5)
    const float gs = __fadd_rn(__fadd_rn(__fadd_rn(__fadd_rn(E0, E1), 1.0f), E1), E0);
    float g1d[5];
    g1d[0] = __fdiv_rn(E0, gs);
    g1d[1] = __fdiv_rn(E1, gs);
    g1d[2] = __fdiv_rn(1.0f, gs);
    g1d[3] = g1d[1];
    g1d[4] = g1d[0];
    float g2d[5][5];
#pragma unroll
    for (int r = 0; r < 5; ++r)
#pragma unroll
        for (int c = 0; c < 5; ++c)
            g2d[r][c] = __fmul_rn(g1d[r], g1d[c]);

    // ---- gray with reflect padding ----
    for (int k = tid; k < 40 * 40; k += 256) {
        int j = k / 40, i = k - j * 40;
        int ry = reflect1024(y0 - 4 + j);
        int rx = reflect1024(x0 - 4 + i);
        int o = ry * W + rx;
        float r = pr[o], g = pr[o + W * H], bl = pr[o + 2 * W * H];
        Sg[j * 44 + i] = __fadd_rn(__fadd_rn(__fmul_rn(0.299f, r), __fmul_rn(0.587f, g)),
                                   __fmul_rn(0.114f, bl));
    }
    __syncthreads();

    // ---- direct 5x5 gaussian at clamped (edge-pad) centers ----
    const bool interior = (blockIdx.x >= 1) && (blockIdx.x <= 30) &&
                          (blockIdx.y >= 1) && (blockIdx.y <= 30);
    if (interior) {
        for (int k = tid; k < 36 * 9; k += 256) {
            int j = k / 9, q = k - j * 9;
            float acc0 = 0.f, acc1 = 0.f, acc2 = 0.f, acc3 = 0.f;
#pragma unroll
            for (int r = 0; r < 5; ++r) {
                float4 A = SgQ[j + r][q];
                float4 B = SgQ[j + r][q + 1];
                float v[8] = {A.x, A.y, A.z, A.w, B.x, B.y, B.z, B.w};
#pragma unroll
                for (int c = 0; c < 5; ++c) {
                    acc0 = fmaf(g2d[r][c], v[c],     acc0);
                    acc1 = fmaf(g2d[r][c], v[c + 1], acc1);
                    acc2 = fmaf(g2d[r][c], v[c + 2], acc2);
                    acc3 = fmaf(g2d[r][c], v[c + 3], acc3);
                }
            }
            Sb[j][4 * q + 0] = acc0;
            Sb[j][4 * q + 1] = acc1;
            Sb[j][4 * q + 2] = acc2;
            Sb[j][4 * q + 3] = acc3;
        }
    } else {
        for (int k = tid; k < 36 * 36; k += 256) {
            int j = k / 36, i = k - j * 36;
            int sj = clamp1024(y0 - 2 + j) - y0 + 4;
            int si = clamp1024(x0 - 2 + i) - x0 + 4;
            float acc = 0.0f;
#pragma unroll
            for (int r = 0; r < 5; ++r)
#pragma unroll
                for (int c = 0; c < 5; ++c)
                    acc = fmaf(g2d[r][c], Sg[(sj - 2 + r) * 44 + (si - 2 + c)], acc);
            Sb[j][i] = acc;
        }
    }
    __syncthreads();

    // ---- sobel + magnitude ----
    for (int k = tid; k < 34 * 34; k += 256) {
        int j = k / 34, i = k - j * 34;
        float a00 = Sb[j][i],     a01 = Sb[j][i + 1],     a02 = Sb[j][i + 2];
        float a10 = Sb[j + 1][i],                         a12 = Sb[j + 1][i + 2];
        float a20 = Sb[j + 2][i], a21 = Sb[j + 2][i + 1], a22 = Sb[j + 2][i + 2];
        float gx = __fadd_rn(__fadd_rn(__fadd_rn(__fadd_rn(__fadd_rn(
                     -a00, a02), __fmul_rn(-2.0f, a10)), __fmul_rn(2.0f, a12)), -a20), a22);
        float gy = __fadd_rn(__fadd_rn(__fadd_rn(__fadd_rn(__fadd_rn(
                     -a00, __fmul_rn(-2.0f, a01)), -a02), a20), __fmul_rn(2.0f, a21)), a22);
        float s = __fadd_rn(__fadd_rn(__fmul_rn(gx, gx), __fmul_rn(gy, gy)), 1e-6f);
        float m = __fsqrt_rn(s);
        int yy = y0 - 1 + j, xx = x0 - 1 + i;
        bool inb = ((unsigned)yy < 1024u) && ((unsigned)xx < 1024u);
        Smag[j][i] = inb ? m : 0.0f;
        Sgx[j][i] = gx;
        Sgy[j][i] = gy;
    }
    __syncthreads();

    // ---- NMS + double threshold; emit magnitude + fill/strong bit planes ----
    unsigned* fillp   = (unsigned*)g_fill;
    unsigned* strongp = (unsigned*)g_strong;
    for (int k = tid; k < 1024; k += 256) {
        int j = k >> 5, i = k & 31;
        float m  = Smag[j + 1][i + 1];
        float gx = Sgx[j + 1][i + 1];
        float gy = Sgy[j + 1][i + 1];
        float ang = __fmul_rn(atan2f(gy, gx), 57.29577951308232087680f);
        int q = (int)rintf(__fdiv_rn(ang, 45.0f));
        int pos = q & 7;
        int neg = (q + 4) & 7;
        float np_ = Smag[j + 1 + c_dy[pos]][i + 1 + c_dx[pos]];
        float nn_ = Smag[j + 1 + c_dy[neg]][i + 1 + c_dx[neg]];
        float mo = (fminf(__fadd_rn(m, -np_), __fadd_rn(m, -nn_)) > 0.0f) ? m : 0.0f;
        int y = y0 + j;
        magout[(b * H + y) * W + x0 + i] = mo;
        unsigned fm = __ballot_sync(0xffffffffu, mo > 0.1f);
        unsigned sm = __ballot_sync(0xffffffffu, mo > 0.2f);
        if (i == 0) {
            int wi = (b * H + y) * (2 * WPR) + (x0 >> 5);
            fillp[wi] = fm;
            strongp[wi] = sm;
        }
    }
}

// =====================================================================
// Kernel B: one bit-parallel hysteresis pass, 64 rows x 1024 cols/block.
// 8 warps; warp wd owns rows [wd*8+1, wd*8+8]. Lanes 0..15 own the 16
// words of a row. Rows in a band are processed sequentially (down, then
// alternating up) so promotions propagate through the whole band within
// one sweep; neighbor words come via warp shuffles; in-word horizontal
// runs flood via wflood. A sweep that changes nothing saw only converged
// values => exact fixed point => deterministic, bit-identical output.
// =====================================================================
__global__ __launch_bounds__(256) void hyst_pass(int pass)
{
    if (pass > 0 && g_changed[pass - 1] == 0) return;

    __shared__ u64 sS[(RT + 2) * P];
    __shared__ u64 sF[(RT + 2) * P];
    __shared__ int s_ch;
    const int tid = threadIdx.x;
    const int b  = blockIdx.x >> 4;
    const int y0 = (blockIdx.x & 15) * RT;

    // load halo tile (rows y0-1 .. y0+RT)
    for (int k = tid; k < (RT + 2) * WPR; k += 256) {
        int r = k >> 4, w = k & (WPR - 1);
        int gy = y0 + r - 1;
        u64 f = 0ull, s = 0ull;
        if ((unsigned)gy < (unsigned)H) {
            int o = (b * H + gy) * WPR + w;
            f = g_fill[o];
            s = g_strong[o];
        }
        sF[r * P + w] = f;
        sS[r * P + w] = s;
    }
    __syncthreads();

    const int wd = tid >> 5;          // warp 0..7, owns rows wd*8+1 .. wd*8+8
    const int lane = tid & 31;
    const int w = lane & 15;
    const bool act = lane < 16;
    const unsigned amask = 0x0000ffffu;

    int any = 0;
    int down = 1;
    for (;;) {
        if (tid == 0) s_ch = 0;
        __syncthreads();
        int ch = 0;
        if (act) {
#pragma unroll 1
            for (int k = 0; k < 8; ++k) {
                int r = down ? (wd * 8 + 1 + k) : (wd * 8 + 8 - k);
                u64 cur   = sS[r * P + w];
                u64 above = sS[(r - 1) * P + w];
                u64 below = sS[(r + 1) * P + w];
                u64 X = above | cur | below;
                u64 XL = __shfl_up_sync(amask, X, 1);
                u64 XR = __shfl_down_sync(amask, X, 1);
                if (w == 0) XL = 0ull;
                if (w == 15) XR = 0ull;
                u64 F = sF[r * P + w];
                if (F != cur) {
                    u64 d = X | (X << 1) | (XL >> 63) | (X >> 1) | (XR << 63);
                    u64 ns = wflood(F, (F & d) | cur);
                    if (ns != cur) { sS[r * P + w] = ns; ch = 1; }
                }
                __syncwarp(amask);
            }
        }
        if (ch) { s_ch = 1; any = 1; }
        __syncthreads();
        if (!s_ch) break;
        down ^= 1;
    }

    if (__syncthreads_or(any)) {
        for (int k = tid; k < RT * WPR; k += 256) {
            int r = (k >> 4) + 1, ww = k & (WPR - 1);
            g_strong[(b * H + y0 + r - 1) * WPR + ww] = sS[r * P + ww];
        }
        if (tid == 0) g_changed[pass] = 1;
    }
}

// =====================================================================
// Kernel C: edges = 1.0 where strong else 0.0
// =====================================================================
__global__ __launch_bounds__(256) void edges_final(float* __restrict__ e)
{
    int i = blockIdx.x * 256 + threadIdx.x;       // over NPIX/4
    unsigned wrd = ((const unsigned*)g_strong)[i >> 3];
    int sh = (i & 7) * 4;
    float4 f;
    f.x = (wrd >> (sh + 0)) & 1u ? 1.0f : 0.0f;
    f.y = (wrd >> (sh + 1)) & 1u ? 1.0f : 0.0f;
    f.z = (wrd >> (sh + 2)) & 1u ? 1.0f : 0.0f;
    f.w = (wrd >> (sh + 3)) & 1u ? 1.0f : 0.0f;
    ((float4*)e)[i] = f;
}

// =====================================================================
extern "C" void kernel_launch(void* const* d_in, const int* in_sizes, int n_in,
                              void* d_out, int out_size)
{
    (void)in_sizes; (void)n_in; (void)out_size;
    const float* x = (const float*)d_in[0];
    float* out = (float*)d_out;          // magnitude (4,1,1024,1024)
    float* edges = out + (size_t)NPIX;   // edges     (4,1,1024,1024)

    dim3 grid(32, 32, NB);
    canny_main<<<grid, 256>>>(x, out);

    for (int p = 0; p < NPASS; ++p)
        hyst_pass<<<HBLOCKS, 256>>>(p);

    edges_final<<<NPIX / 1024, 256>>>(edges);
}

// round 7
// speedup vs baseline: 1.2155x; 1.1510x over previous
#include <cuda_runtime.h>
#include <math.h>

#define W 1024
#define H 1024
#define NB 4
#define NPIX (NB * W * H)

#define NPASS 6
#define RT 64                       // hysteresis rows per tile
#define HBLOCKS (NB * H / RT)       // 64 blocks
#define WPR 16                      // u64 words per row (1024 bits)
#define P (WPR + 1)

typedef unsigned long long u64;

// ---------------- device scratch (no runtime allocation) ----------------
__device__ u64 g_fill[NB * H * WPR];    // weak-or-strong bits
__device__ u64 g_strong[NB * H * WPR];  // strong bits (grows monotonically)
__device__ int g_changed[NPASS];

__constant__ int c_dy[8] = {0, -1, -1, -1, 0, 1, 1, 1};
__constant__ int c_dx[8] = {1,  1,  0, -1, -1, -1, 0, 1};

__device__ __forceinline__ int reflect1024(int t) {
    t = (t < 0) ? -t : t;
    return (t > 1023) ? (2046 - t) : t;
}
__device__ __forceinline__ int clamp1024(int t) {
    return (t < 0) ? 0 : ((t > 1023) ? 1023 : t);
}

// In-word bidirectional flood of seeds through runs of F.
// Returns ns with seed ⊆ ns ⊆ (bits of F connected-in-word to a seed).
__device__ __forceinline__ u64 wflood(u64 F, u64 seed) {
    u64 t = seed & F;
    u64 up = (((F + t) ^ F) & F) | t;          // toward MSB
    u64 Fr = __brevll(F), sr = __brevll(up);
    u64 tr = sr & Fr;
    u64 dn = (((Fr + tr) ^ Fr) & Fr) | tr;     // toward LSB of original
    return __brevll(dn);
}

// =====================================================================
// Kernel A: gray -> 5x5 gaussian (direct, row-major FMA) -> sobel ->
//           magnitude -> NMS -> double threshold (bit planes out).
//           32x32 tile, halo 4. Arithmetic identical to R2/R3.
// =====================================================================
__global__ __launch_bounds__(256) void canny_main(const float* __restrict__ in,
                                                  float* __restrict__ magout)
{
    __shared__ float4 SgQ[40][11];   // gray, pitch 44 floats
    __shared__ float Sb[36][37];
    __shared__ float Smag[34][35];
    __shared__ float Sgx[34][35];
    __shared__ float Sgy[34][35];
    float* Sg = (float*)SgQ;

    const int tid = threadIdx.x;
    const int b  = blockIdx.z;
    const int y0 = blockIdx.y << 5;
    const int x0 = blockIdx.x << 5;
    const float* pr = in + (size_t)b * 3 * W * H;

    if (b == 0 && blockIdx.x == 0 && blockIdx.y == 0 && tid < NPASS)
        g_changed[tid] = 0;

    const float E0 = 0.13533528323661270231f;   // exp(-2)
    const float E1 = 0.60653065971263342360f;   // exp(-0.5)
    const float gs = __fadd_rn(__fadd_rn(__fadd_rn(__fadd_rn(E0, E1), 1.0f), E1), E0);
    float g1d[5];
    g1d[0] = __fdiv_rn(E0, gs);
    g1d[1] = __fdiv_rn(E1, gs);
    g1d[2] = __fdiv_rn(1.0f, gs);
    g1d[3] = g1d[1];
    g1d[4] = g1d[0];
    float g2d[5][5];
#pragma unroll
    for (int r = 0; r < 5; ++r)
#pragma unroll
        for (int c = 0; c < 5; ++c)
            g2d[r][c] = __fmul_rn(g1d[r], g1d[c]);

    // ---- gray with reflect padding ----
    for (int k = tid; k < 40 * 40; k += 256) {
        int j = k / 40, i = k - j * 40;
        int ry = reflect1024(y0 - 4 + j);
        int rx = reflect1024(x0 - 4 + i);
        int o = ry * W + rx;
        float r = pr[o], g = pr[o + W * H], bl = pr[o + 2 * W * H];
        Sg[j * 44 + i] = __fadd_rn(__fadd_rn(__fmul_rn(0.299f, r), __fmul_rn(0.587f, g)),
                                   __fmul_rn(0.114f, bl));
    }
    __syncthreads();

    // ---- direct 5x5 gaussian at clamped (edge-pad) centers ----
    const bool interior = (blockIdx.x >= 1) && (blockIdx.x <= 30) &&
                          (blockIdx.y >= 1) && (blockIdx.y <= 30);
    if (interior) {
        for (int k = tid; k < 36 * 9; k += 256) {
            int j = k / 9, q = k - j * 9;
            float acc0 = 0.f, acc1 = 0.f, acc2 = 0.f, acc3 = 0.f;
#pragma unroll
            for (int r = 0; r < 5; ++r) {
                float4 A = SgQ[j + r][q];
                float4 B = SgQ[j + r][q + 1];
                float v[8] = {A.x, A.y, A.z, A.w, B.x, B.y, B.z, B.w};
#pragma unroll
                for (int c = 0; c < 5; ++c) {
                    acc0 = fmaf(g2d[r][c], v[c],     acc0);
                    acc1 = fmaf(g2d[r][c], v[c + 1], acc1);
                    acc2 = fmaf(g2d[r][c], v[c + 2], acc2);
                    acc3 = fmaf(g2d[r][c], v[c + 3], acc3);
                }
            }
            Sb[j][4 * q + 0] = acc0;
            Sb[j][4 * q + 1] = acc1;
            Sb[j][4 * q + 2] = acc2;
            Sb[j][4 * q + 3] = acc3;
        }
    } else {
        for (int k = tid; k < 36 * 36; k += 256) {
            int j = k / 36, i = k - j * 36;
            int sj = clamp1024(y0 - 2 + j) - y0 + 4;
            int si = clamp1024(x0 - 2 + i) - x0 + 4;
            float acc = 0.0f;
#pragma unroll
            for (int r = 0; r < 5; ++r)
#pragma unroll
                for (int c = 0; c < 5; ++c)
                    acc = fmaf(g2d[r][c], Sg[(sj - 2 + r) * 44 + (si - 2 + c)], acc);
            Sb[j][i] = acc;
        }
    }
    __syncthreads();

    // ---- sobel + magnitude ----
    for (int k = tid; k < 34 * 34; k += 256) {
        int j = k / 34, i = k - j * 34;
        float a00 = Sb[j][i],     a01 = Sb[j][i + 1],     a02 = Sb[j][i + 2];
        float a10 = Sb[j + 1][i],                         a12 = Sb[j + 1][i + 2];
        float a20 = Sb[j + 2][i], a21 = Sb[j + 2][i + 1], a22 = Sb[j + 2][i + 2];
        float gx = __fadd_rn(__fadd_rn(__fadd_rn(__fadd_rn(__fadd_rn(
                     -a00, a02), __fmul_rn(-2.0f, a10)), __fmul_rn(2.0f, a12)), -a20), a22);
        float gy = __fadd_rn(__fadd_rn(__fadd_rn(__fadd_rn(__fadd_rn(
                     -a00, __fmul_rn(-2.0f, a01)), -a02), a20), __fmul_rn(2.0f, a21)), a22);
        float s = __fadd_rn(__fadd_rn(__fmul_rn(gx, gx), __fmul_rn(gy, gy)), 1e-6f);
        float m = __fsqrt_rn(s);
        int yy = y0 - 1 + j, xx = x0 - 1 + i;
        bool inb = ((unsigned)yy < 1024u) && ((unsigned)xx < 1024u);
        Smag[j][i] = inb ? m : 0.0f;
        Sgx[j][i] = gx;
        Sgy[j][i] = gy;
    }
    __syncthreads();

    // ---- NMS + double threshold; emit magnitude + fill/strong bit planes ----
    unsigned* fillp   = (unsigned*)g_fill;
    unsigned* strongp = (unsigned*)g_strong;
    for (int k = tid; k < 1024; k += 256) {
        int j = k >> 5, i = k & 31;
        float m  = Smag[j + 1][i + 1];
        float gx = Sgx[j + 1][i + 1];
        float gy = Sgy[j + 1][i + 1];
        float ang = __fmul_rn(atan2f(gy, gx), 57.29577951308232087680f);
        int q = (int)rintf(__fdiv_rn(ang, 45.0f));
        int pos = q & 7;
        int neg = (q + 4) & 7;
        float np_ = Smag[j + 1 + c_dy[pos]][i + 1 + c_dx[pos]];
        float nn_ = Smag[j + 1 + c_dy[neg]][i + 1 + c_dx[neg]];
        float mo = (fminf(__fadd_rn(m, -np_), __fadd_rn(m, -nn_)) > 0.0f) ? m : 0.0f;
        int y = y0 + j;
        magout[(b * H + y) * W + x0 + i] = mo;
        unsigned fm = __ballot_sync(0xffffffffu, mo > 0.1f);
        unsigned sm = __ballot_sync(0xffffffffu, mo > 0.2f);
        if (i == 0) {
            int wi = (b * H + y) * (2 * WPR) + (x0 >> 5);
            fillp[wi] = fm;
            strongp[wi] = sm;
        }
    }
}

// =====================================================================
// Kernel B: one bit-parallel hysteresis pass (R3 Jacobi structure).
// 64 rows x 1024 cols per block; thread owns 4 consecutive rows x 1 word
// (registers, write-through to smem). Per sweep: register Gauss-Seidel
// through the 4 owned rows (alternating direction), wflood for in-word
// horizontal runs. One sweep per barrier. A sweep that changes nothing
// read only converged values => exact fixed point => deterministic.
// =====================================================================
__global__ __launch_bounds__(256) void hyst_pass(int pass)
{
    if (pass > 0 && g_changed[pass - 1] == 0) return;

    __shared__ u64 sS[(RT + 2) * P];
    __shared__ u64 sF[(RT + 2) * P];
    const int tid = threadIdx.x;
    const int b  = blockIdx.x >> 4;
    const int y0 = (blockIdx.x & 15) * RT;

    // load halo tile (rows y0-1 .. y0+RT)
    for (int k = tid; k < (RT + 2) * WPR; k += 256) {
        int r = k >> 4, w = k & (WPR - 1);
        int gy = y0 + r - 1;
        u64 f = 0ull, s = 0ull;
        if ((unsigned)gy < (unsigned)H) {
            int o = (b * H + gy) * WPR + w;
            f = g_fill[o];
            s = g_strong[o];
        }
        sF[r * P + w] = f;
        sS[r * P + w] = s;
    }
    __syncthreads();

    const int w  = tid & 15;
    const int r0 = ((tid >> 4) << 2) + 1;    // owns rows r0..r0+3 (1..64)
    u64 F[4], S[4];
#pragma unroll
    for (int i = 0; i < 4; ++i) {
        F[i] = sF[(r0 + i) * P + w];
        S[i] = sS[(r0 + i) * P + w];
    }

    int any = 0;
    int down = 1;
    for (;;) {
        int ch = 0;
#pragma unroll
        for (int ii = 0; ii < 4; ++ii) {
            int i = down ? ii : (3 - ii);
            u64 Fi = F[i];
            u64 cur = S[i];
            if (Fi == cur) continue;
            int r = r0 + i;
            u64 above = (i > 0) ? S[i - 1] : sS[(r - 1) * P + w];
            u64 below = (i < 3) ? S[i + 1] : sS[(r + 1) * P + w];
            u64 X = above | cur | below;
            u64 XL = (w > 0)
                ? (sS[(r - 1) * P + w - 1] | sS[r * P + w - 1] | sS[(r + 1) * P + w - 1])
                : 0ull;
            u64 XR = (w < WPR - 1)
                ? (sS[(r - 1) * P + w + 1] | sS[r * P + w + 1] | sS[(r + 1) * P + w + 1])
                : 0ull;
            u64 d = X | (X << 1) | (XL >> 63) | (X >> 1) | (XR << 63);
            u64 ns = wflood(Fi, (Fi & d) | cur);
            if (ns != cur) {
                S[i] = ns;
                sS[r * P + w] = ns;
                ch = 1;
            }
        }
        down ^= 1;
        any |= ch;
        if (!__syncthreads_or(ch)) break;
    }

    if (__syncthreads_or(any)) {
#pragma unroll
        for (int i = 0; i < 4; ++i)
            g_strong[(b * H + y0 + r0 + i - 1) * WPR + w] = S[i];
        if (tid == 0) g_changed[pass] = 1;
    }
}

// =====================================================================
// Kernel C: edges = 1.0 where strong else 0.0
// =====================================================================
__global__ __launch_bounds__(256) void edges_final(float* __restrict__ e)
{
    int i = blockIdx.x * 256 + threadIdx.x;       // over NPIX/4
    unsigned wrd = ((const unsigned*)g_strong)[i >> 3];
    int sh = (i & 7) * 4;
    float4 f;
    f.x = (wrd >> (sh + 0)) & 1u ? 1.0f : 0.0f;
    f.y = (wrd >> (sh + 1)) & 1u ? 1.0f : 0.0f;
    f.z = (wrd >> (sh + 2)) & 1u ? 1.0f : 0.0f;
    f.w = (wrd >> (sh + 3)) & 1u ? 1.0f : 0.0f;
    ((float4*)e)[i] = f;
}

// =====================================================================
extern "C" void kernel_launch(void* const* d_in, const int* in_sizes, int n_in,
                              void* d_out, int out_size)
{
    (void)in_sizes; (void)n_in; (void)out_size;
    const float* x = (const float*)d_in[0];
    float* out = (float*)d_out;          // magnitude (4,1,1024,1024)
    float* edges = out + (size_t)NPIX;   // edges     (4,1,1024,1024)

    dim3 grid(32, 32, NB);
    canny_main<<<grid, 256>>>(x, out);

    for (int p = 0; p < NPASS; ++p)
        hyst_pass<<<HBLOCKS, 256>>>(p);

    edges_final<<<NPIX / 1024, 256>>>(edges);
}

// round 10
// speedup vs baseline: 1.4033x; 1.1544x over previous
#include <cuda_runtime.h>
#include <math.h>

#define W 1024
#define H 1024
#define NB 4
#define NPIX (NB * W * H)

#define NPASS 6
#define RT 16                       // hysteresis rows per tile
#define HBLOCKS (NB * H / RT)       // 256 blocks
#define WPR 16                      // u64 words per row (1024 bits)
#define P (WPR + 1)

typedef unsigned long long u64;

// ---------------- device scratch (no runtime allocation) ----------------
__device__ u64 g_fill[NB * H * WPR];    // weak-or-strong bits
__device__ u64 g_strong[NB * H * WPR];  // strong bits (grows monotonically)
__device__ int g_changed[NPASS];

__constant__ int c_dy[8] = {0, -1, -1, -1, 0, 1, 1, 1};
__constant__ int c_dx[8] = {1,  1,  0, -1, -1, -1, 0, 1};

__device__ __forceinline__ int reflect1024(int t) {
    t = (t < 0) ? -t : t;
    return (t > 1023) ? (2046 - t) : t;
}
__device__ __forceinline__ int clamp1024(int t) {
    return (t < 0) ? 0 : ((t > 1023) ? 1023 : t);
}

// In-word bidirectional flood of seeds through runs of F.
// Returns ns with seed ⊆ ns ⊆ (bits of F connected-in-word to a seed).
__device__ __forceinline__ u64 wflood(u64 F, u64 seed) {
    u64 t = seed & F;
    u64 up = (((F + t) ^ F) & F) | t;          // toward MSB
    u64 Fr = __brevll(F), sr = __brevll(up);
    u64 tr = sr & Fr;
    u64 dn = (((Fr + tr) ^ Fr) & Fr) | tr;     // toward LSB of original
    return __brevll(dn);
}

// =====================================================================
// Kernel A: gray -> 5x5 gaussian (direct, row-major FMA) -> sobel ->
//           magnitude -> NMS -> double threshold (bit planes out).
//           32x32 tile, halo 4. Arithmetic identical to R2..R7.
// =====================================================================
__global__ __launch_bounds__(256) void canny_main(const float* __restrict__ in,
                                                  float* __restrict__ magout)
{
    __shared__ float4 SgQ[40][11];   // gray, pitch 44 floats
    __shared__ float Sb[36][37];
    __shared__ float Smag[34][35];
    __shared__ float Sgx[34][35];
    __shared__ float Sgy[34][35];
    float* Sg = (float*)SgQ;

    const int tid = threadIdx.x;
    const int b  = blockIdx.z;
    const int y0 = blockIdx.y << 5;
    const int x0 = blockIdx.x << 5;
    const float* pr = in + (size_t)b * 3 * W * H;

    if (b == 0 && blockIdx.x == 0 && blockIdx.y == 0 && tid < NPASS)
        g_changed[tid] = 0;

    const float E0 = 0.13533528323661270231f;   // exp(-2)
    const float E1 = 0.60653065971263342360f;   // exp(-0.5)
    const float gs = __fadd_rn(__fadd_rn(__fadd_rn(__fadd_rn(E0, E1), 1.0f), E1), E0);
    float g1d[5];
    g1d[0] = __fdiv_rn(E0, gs);
    g1d[1] = __fdiv_rn(E1, gs);
    g1d[2] = __fdiv_rn(1.0f, gs);
    g1d[3] = g1d[1];
    g1d[4] = g1d[0];
    float g2d[5][5];
#pragma unroll
    for (int r = 0; r < 5; ++r)
#pragma unroll
        for (int c = 0; c < 5; ++c)
            g2d[r][c] = __fmul_rn(g1d[r], g1d[c]);

    // ---- gray with reflect padding ----
    for (int k = tid; k < 40 * 40; k += 256) {
        int j = k / 40, i = k - j * 40;
        int ry = reflect1024(y0 - 4 + j);
        int rx = reflect1024(x0 - 4 + i);
        int o = ry * W + rx;
        float r = pr[o], g = pr[o + W * H], bl = pr[o + 2 * W * H];
        Sg[j * 44 + i] = __fadd_rn(__fadd_rn(__fmul_rn(0.299f, r), __fmul_rn(0.587f, g)),
                                   __fmul_rn(0.114f, bl));
    }
    __syncthreads();

    // ---- direct 5x5 gaussian at clamped (edge-pad) centers ----
    const bool interior = (blockIdx.x >= 1) && (blockIdx.x <= 30) &&
                          (blockIdx.y >= 1) && (blockIdx.y <= 30);
    if (interior) {
        for (int k = tid; k < 36 * 9; k += 256) {
            int j = k / 9, q = k - j * 9;
            float acc0 = 0.f, acc1 = 0.f, acc2 = 0.f, acc3 = 0.f;
#pragma unroll
            for (int r = 0; r < 5; ++r) {
                float4 A = SgQ[j + r][q];
                float4 B = SgQ[j + r][q + 1];
                float v[8] = {A.x, A.y, A.z, A.w, B.x, B.y, B.z, B.w};
#pragma unroll
                for (int c = 0; c < 5; ++c) {
                    acc0 = fmaf(g2d[r][c], v[c],     acc0);
                    acc1 = fmaf(g2d[r][c], v[c + 1], acc1);
                    acc2 = fmaf(g2d[r][c], v[c + 2], acc2);
                    acc3 = fmaf(g2d[r][c], v[c + 3], acc3);
                }
            }
            Sb[j][4 * q + 0] = acc0;
            Sb[j][4 * q + 1] = acc1;
            Sb[j][4 * q + 2] = acc2;
            Sb[j][4 * q + 3] = acc3;
        }
    } else {
        for (int k = tid; k < 36 * 36; k += 256) {
            int j = k / 36, i = k - j * 36;
            int sj = clamp1024(y0 - 2 + j) - y0 + 4;
            int si = clamp1024(x0 - 2 + i) - x0 + 4;
            float acc = 0.0f;
#pragma unroll
            for (int r = 0; r < 5; ++r)
#pragma unroll
                for (int c = 0; c < 5; ++c)
                    acc = fmaf(g2d[r][c], Sg[(sj - 2 + r) * 44 + (si - 2 + c)], acc);
            Sb[j][i] = acc;
        }
    }
    __syncthreads();

    // ---- sobel + magnitude ----
    for (int k = tid; k < 34 * 34; k += 256) {
        int j = k / 34, i = k - j * 34;
        float a00 = Sb[j][i],     a01 = Sb[j][i + 1],     a02 = Sb[j][i + 2];
        float a10 = Sb[j + 1][i],                         a12 = Sb[j + 1][i + 2];
        float a20 = Sb[j + 2][i], a21 = Sb[j + 2][i + 1], a22 = Sb[j + 2][i + 2];
        float gx = __fadd_rn(__fadd_rn(__fadd_rn(__fadd_rn(__fadd_rn(
                     -a00, a02), __fmul_rn(-2.0f, a10)), __fmul_rn(2.0f, a12)), -a20), a22);
        float gy = __fadd_rn(__fadd_rn(__fadd_rn(__fadd_rn(__fadd_rn(
                     -a00, __fmul_rn(-2.0f, a01)), -a02), a20), __fmul_rn(2.0f, a21)), a22);
        float s = __fadd_rn(__fadd_rn(__fmul_rn(gx, gx), __fmul_rn(gy, gy)), 1e-6f);
        float m = __fsqrt_rn(s);
        int yy = y0 - 1 + j, xx = x0 - 1 + i;
        bool inb = ((unsigned)yy < 1024u) && ((unsigned)xx < 1024u);
        Smag[j][i] = inb ? m : 0.0f;
        Sgx[j][i] = gx;
        Sgy[j][i] = gy;
    }
    __syncthreads();

    // ---- NMS + double threshold; emit magnitude + fill/strong bit planes ----
    unsigned* fillp   = (unsigned*)g_fill;
    unsigned* strongp = (unsigned*)g_strong;
    for (int k = tid; k < 1024; k += 256) {
        int j = k >> 5, i = k & 31;
        float m  = Smag[j + 1][i + 1];
        float gx = Sgx[j + 1][i + 1];
        float gy = Sgy[j + 1][i + 1];
        float ang = __fmul_rn(atan2f(gy, gx), 57.29577951308232087680f);
        int q = (int)rintf(__fdiv_rn(ang, 45.0f));
        int pos = q & 7;
        int neg = (q + 4) & 7;
        float np_ = Smag[j + 1 + c_dy[pos]][i + 1 + c_dx[pos]];
        float nn_ = Smag[j + 1 + c_dy[neg]][i + 1 + c_dx[neg]];
        float mo = (fminf(__fadd_rn(m, -np_), __fadd_rn(m, -nn_)) > 0.0f) ? m : 0.0f;
        int y = y0 + j;
        magout[(b * H + y) * W + x0 + i] = mo;
        unsigned fm = __ballot_sync(0xffffffffu, mo > 0.1f);
        unsigned sm = __ballot_sync(0xffffffffu, mo > 0.2f);
        if (i == 0) {
            int wi = (b * H + y) * (2 * WPR) + (x0 >> 5);
            fillp[wi] = fm;
            strongp[wi] = sm;
        }
    }
}

// =====================================================================
// Kernel B: one bit-parallel hysteresis pass. 16 rows x 1024 cols per
// block (256 blocks -> full SM coverage); one u64 word per thread.
// Jacobi sweeps with in-word wflood; one barrier per sweep. A sweep
// that changes nothing read only converged values => exact fixed point
// of the basic operator => deterministic, bit-identical output.
// =====================================================================
__global__ __launch_bounds__(256) void hyst_pass(int pass)
{
    if (pass > 0 && g_changed[pass - 1] == 0) return;

    __shared__ u64 sS[(RT + 2) * P];
    __shared__ u64 sF[(RT + 2) * P];
    const int tid = threadIdx.x;
    const int b  = blockIdx.x >> 6;              // 64 tiles per batch
    const int y0 = (blockIdx.x & 63) * RT;

    // load halo tile (rows y0-1 .. y0+RT)
    for (int k = tid; k < (RT + 2) * WPR; k += 256) {
        int r = k >> 4, w = k & (WPR - 1);
        int gy = y0 + r - 1;
        u64 f = 0ull, s = 0ull;
        if ((unsigned)gy < (unsigned)H) {
            int o = (b * H + gy) * WPR + w;
            f = g_fill[o];
            s = g_strong[o];
        }
        sF[r * P + w] = f;
        sS[r * P + w] = s;
    }
    __syncthreads();

    const int w = tid & 15;
    const int r = (tid >> 4) + 1;               // rows 1..16, one per thread
    const u64 F = sF[r * P + w];
    u64 S = sS[r * P + w];

    int any = 0;
    for (;;) {
        int ch = 0;
        if (F != S) {
            u64 above = sS[(r - 1) * P + w];
            u64 below = sS[(r + 1) * P + w];
            u64 X = above | S | below;
            u64 XL = (w > 0)
                ? (sS[(r - 1) * P + w - 1] | sS[r * P + w - 1] | sS[(r + 1) * P + w - 1])
                : 0ull;
            u64 XR = (w < WPR - 1)
                ? (sS[(r - 1) * P + w + 1] | sS[r * P + w + 1] | sS[(r + 1) * P + w + 1])
                : 0ull;
            u64 d = X | (X << 1) | (XL >> 63) | (X >> 1) | (XR << 63);
            u64 ns = wflood(F, (F & d) | S);
            if (ns != S) {
                S = ns;
                sS[r * P + w] = ns;
                ch = 1;
            }
        }
        any |= ch;
        if (!__syncthreads_or(ch)) break;
    }

    if (__syncthreads_or(any)) {
        g_strong[(b * H + y0 + r - 1) * WPR + w] = S;
        if (tid == 0) g_changed[pass] = 1;
    }
}

// =====================================================================
// Kernel C: edges = 1.0 where strong else 0.0
// =====================================================================
__global__ __launch_bounds__(256) void edges_final(float* __restrict__ e)
{
    int i = blockIdx.x * 256 + threadIdx.x;       // over NPIX/4
    unsigned wrd = ((const unsigned*)g_strong)[i >> 3];
    int sh = (i & 7) * 4;
    float4 f;
    f.x = (wrd >> (sh + 0)) & 1u ? 1.0f : 0.0f;
    f.y = (wrd >> (sh + 1)) & 1u ? 1.0f : 0.0f;
    f.z = (wrd >> (sh + 2)) & 1u ? 1.0f : 0.0f;
    f.w = (wrd >> (sh + 3)) & 1u ? 1.0f : 0.0f;
    ((float4*)e)[i] = f;
}

// =====================================================================
extern "C" void kernel_launch(void* const* d_in, const int* in_sizes, int n_in,
                              void* d_out, int out_size)
{
    (void)in_sizes; (void)n_in; (void)out_size;
    const float* x = (const float*)d_in[0];
    float* out = (float*)d_out;          // magnitude (4,1,1024,1024)
    float* edges = out + (size_t)NPIX;   // edges     (4,1,1024,1024)

    dim3 grid(32, 32, NB);
    canny_main<<<grid, 256>>>(x, out);

    for (int p = 0; p < NPASS; ++p)
        hyst_pass<<<HBLOCKS, 256>>>(p);

    edges_final<<<NPIX / 1024, 256>>>(edges);
}

// round 11
// speedup vs baseline: 1.4352x; 1.0227x over previous
#include <cuda_runtime.h>
#include <math.h>

#define W 1024
#define H 1024
#define NB 4
#define NPIX (NB * W * H)

#define NPASS 6
#define RT 16                       // hysteresis rows per strip
#define HBLOCKS (NB * H / RT)       // 256 strips (full width)
#define SPB 64                      // strips per batch
#define WPR 16                      // u64 words per row (1024 bits)
#define P (WPR + 1)

typedef unsigned long long u64;

// ---------------- device scratch (no runtime allocation) ----------------
__device__ u64 g_fill[NB * H * WPR];    // weak-or-strong bits
__device__ u64 g_strong[NB * H * WPR];  // strong bits (grows monotonically)
__device__ int g_dirty[NPASS][HBLOCKS]; // strip changed in pass p

__constant__ int c_dy[8] = {0, -1, -1, -1, 0, 1, 1, 1};
__constant__ int c_dx[8] = {1,  1,  0, -1, -1, -1, 0, 1};

__device__ __forceinline__ int reflect1024(int t) {
    t = (t < 0) ? -t : t;
    return (t > 1023) ? (2046 - t) : t;
}
__device__ __forceinline__ int clamp1024(int t) {
    return (t < 0) ? 0 : ((t > 1023) ? 1023 : t);
}

// In-word bidirectional flood of seeds through runs of F.
__device__ __forceinline__ u64 wflood(u64 F, u64 seed) {
    u64 t = seed & F;
    u64 up = (((F + t) ^ F) & F) | t;          // toward MSB
    u64 Fr = __brevll(F), sr = __brevll(up);
    u64 tr = sr & Fr;
    u64 dn = (((Fr + tr) ^ Fr) & Fr) | tr;     // toward LSB of original
    return __brevll(dn);
}

// =====================================================================
// Kernel A: gray -> 5x5 gaussian -> sobel -> magnitude -> NMS ->
//           double threshold (bit planes out). 32x32 tile, halo 4.
//           All arithmetic identical to R2..R10; the NMS direction q is
//           computed by an exact octant classifier with atan2f fallback
//           inside +-0.1% guard bands (provably same q&7 everywhere).
// =====================================================================
__global__ __launch_bounds__(256) void canny_main(const float* __restrict__ in,
                                                  float* __restrict__ magout)
{
    __shared__ float4 SgQ[40][11];   // gray, pitch 44 floats
    __shared__ float Sb[36][37];
    __shared__ float Smag[34][35];
    __shared__ float Sgx[34][35];
    __shared__ float Sgy[34][35];
    float* Sg = (float*)SgQ;

    const int tid = threadIdx.x;
    const int b  = blockIdx.z;
    const int y0 = blockIdx.y << 5;
    const int x0 = blockIdx.x << 5;
    const float* pr = in + (size_t)b * 3 * W * H;

    if (b == 0 && blockIdx.x == 0 && blockIdx.y == 0) {
        for (int k = tid; k < NPASS * HBLOCKS; k += 256)
            ((int*)g_dirty)[k] = 0;
    }

    const float E0 = 0.13533528323661270231f;   // exp(-2)
    const float E1 = 0.60653065971263342360f;   // exp(-0.5)
    const float gs = __fadd_rn(__fadd_rn(__fadd_rn(__fadd_rn(E0, E1), 1.0f), E1), E0);
    float g1d[5];
    g1d[0] = __fdiv_rn(E0, gs);
    g1d[1] = __fdiv_rn(E1, gs);
    g1d[2] = __fdiv_rn(1.0f, gs);
    g1d[3] = g1d[1];
    g1d[4] = g1d[0];
    float g2d[5][5];
#pragma unroll
    for (int r = 0; r < 5; ++r)
#pragma unroll
        for (int c = 0; c < 5; ++c)
            g2d[r][c] = __fmul_rn(g1d[r], g1d[c]);

    // ---- gray with reflect padding ----
    for (int k = tid; k < 40 * 40; k += 256) {
        int j = k / 40, i = k - j * 40;
        int ry = reflect1024(y0 - 4 + j);
        int rx = reflect1024(x0 - 4 + i);
        int o = ry * W + rx;
        float r = pr[o], g = pr[o + W * H], bl = pr[o + 2 * W * H];
        Sg[j * 44 + i] = __fadd_rn(__fadd_rn(__fmul_rn(0.299f, r), __fmul_rn(0.587f, g)),
                                   __fmul_rn(0.114f, bl));
    }
    __syncthreads();

    // ---- direct 5x5 gaussian at clamped (edge-pad) centers ----
    const bool interior = (blockIdx.x >= 1) && (blockIdx.x <= 30) &&
                          (blockIdx.y >= 1) && (blockIdx.y <= 30);
    if (interior) {
        for (int k = tid; k < 36 * 9; k += 256) {
            int j = k / 9, q = k - j * 9;
            float acc0 = 0.f, acc1 = 0.f, acc2 = 0.f, acc3 = 0.f;
#pragma unroll
            for (int r = 0; r < 5; ++r) {
                float4 A = SgQ[j + r][q];
                float4 B = SgQ[j + r][q + 1];
                float v[8] = {A.x, A.y, A.z, A.w, B.x, B.y, B.z, B.w};
#pragma unroll
                for (int c = 0; c < 5; ++c) {
                    acc0 = fmaf(g2d[r][c], v[c],     acc0);
                    acc1 = fmaf(g2d[r][c], v[c + 1], acc1);
                    acc2 = fmaf(g2d[r][c], v[c + 2], acc2);
                    acc3 = fmaf(g2d[r][c], v[c + 3], acc3);
                }
            }
            Sb[j][4 * q + 0] = acc0;
            Sb[j][4 * q + 1] = acc1;
            Sb[j][4 * q + 2] = acc2;
            Sb[j][4 * q + 3] = acc3;
        }
    } else {
        for (int k = tid; k < 36 * 36; k += 256) {
            int j = k / 36, i = k - j * 36;
            int sj = clamp1024(y0 - 2 + j) - y0 + 4;
            int si = clamp1024(x0 - 2 + i) - x0 + 4;
            float acc = 0.0f;
#pragma unroll
            for (int r = 0; r < 5; ++r)
#pragma unroll
                for (int c = 0; c < 5; ++c)
                    acc = fmaf(g2d[r][c], Sg[(sj - 2 + r) * 44 + (si - 2 + c)], acc);
            Sb[j][i] = acc;
        }
    }
    __syncthreads();

    // ---- sobel + magnitude ----
    for (int k = tid; k < 34 * 34; k += 256) {
        int j = k / 34, i = k - j * 34;
        float a00 = Sb[j][i],     a01 = Sb[j][i + 1],     a02 = Sb[j][i + 2];
        float a10 = Sb[j + 1][i],                         a12 = Sb[j + 1][i + 2];
        float a20 = Sb[j + 2][i], a21 = Sb[j + 2][i + 1], a22 = Sb[j + 2][i + 2];
        float gx = __fadd_rn(__fadd_rn(__fadd_rn(__fadd_rn(__fadd_rn(
                     -a00, a02), __fmul_rn(-2.0f, a10)), __fmul_rn(2.0f, a12)), -a20), a22);
        float gy = __fadd_rn(__fadd_rn(__fadd_rn(__fadd_rn(__fadd_rn(
                     -a00, __fmul_rn(-2.0f, a01)), -a02), a20), __fmul_rn(2.0f, a21)), a22);
        float s = __fadd_rn(__fadd_rn(__fmul_rn(gx, gx), __fmul_rn(gy, gy)), 1e-6f);
        float m = __fsqrt_rn(s);
        int yy = y0 - 1 + j, xx = x0 - 1 + i;
        bool inb = ((unsigned)yy < 1024u) && ((unsigned)xx < 1024u);
        Smag[j][i] = inb ? m : 0.0f;
        Sgx[j][i] = gx;
        Sgy[j][i] = gy;
    }
    __syncthreads();

    // ---- NMS + double threshold; emit magnitude + fill/strong bit planes ----
    unsigned* fillp   = (unsigned*)g_fill;
    unsigned* strongp = (unsigned*)g_strong;
    // guard-banded octant thresholds (0.1% bands; compile-time folded)
    const float T22LO = 0.41421356237309515f * 0.999f;
    const float T22HI = 0.41421356237309515f * 1.001f;
    const float T67LO = 2.41421356237309515f * 0.999f;
    const float T67HI = 2.41421356237309515f * 1.001f;
    for (int k = tid; k < 1024; k += 256) {
        int j = k >> 5, i = k & 31;
        float m  = Smag[j + 1][i + 1];
        float gx = Sgx[j + 1][i + 1];
        float gy = Sgy[j + 1][i + 1];
        float ax = fabsf(gx), ay = fabsf(gy);
        bool gxn = gx < 0.0f, gyn = gy < 0.0f;
        int pos;
        if (ay < ax * T22LO) {                       // |ang| near 0/180
            pos = gxn ? 4 : 0;
        } else if (ay > ax * T67HI) {                // |ang| near 90
            pos = gyn ? 6 : 2;
        } else if (ay > ax * T22HI && ay < ax * T67LO) {   // diagonal octants
            pos = gyn ? (gxn ? 5 : 7) : (gxn ? 3 : 1);
        } else {
            // within guard band: original computation, bit-exact
            float ang = __fmul_rn(atan2f(gy, gx), 57.29577951308232087680f);
            int q = (int)rintf(__fdiv_rn(ang, 45.0f));
            pos = q & 7;
        }
        int neg = pos ^ 4;
        float np_ = Smag[j + 1 + c_dy[pos]][i + 1 + c_dx[pos]];
        float nn_ = Smag[j + 1 + c_dy[neg]][i + 1 + c_dx[neg]];
        float mo = (fminf(__fadd_rn(m, -np_), __fadd_rn(m, -nn_)) > 0.0f) ? m : 0.0f;
        int y = y0 + j;
        magout[(b * H + y) * W + x0 + i] = mo;
        unsigned fm = __ballot_sync(0xffffffffu, mo > 0.1f);
        unsigned sm = __ballot_sync(0xffffffffu, mo > 0.2f);
        if (i == 0) {
            int wi = (b * H + y) * (2 * WPR) + (x0 >> 5);
            fillp[wi] = fm;
            strongp[wi] = sm;
        }
    }
}

// =====================================================================
// Kernel B: one bit-parallel hysteresis pass over full-width 16-row
// strips. Pass p>0 runs a strip only if it or a vertical neighbor was
// dirty in pass p-1 (skipped strips have unchanged inputs => exact).
// Jacobi sweeps with in-word wflood; quiescent sweep => exact fixed
// point of the basic operator => deterministic, bit-identical output.
// =====================================================================
__global__ __launch_bounds__(256) void hyst_pass(int pass)
{
    const int t = blockIdx.x;                    // strip id
    const int s = t & (SPB - 1);                 // strip within batch
    if (pass > 0) {
        const int* prev = g_dirty[pass - 1];
        bool run = prev[t] != 0;
        if (s > 0)       run |= prev[t - 1] != 0;
        if (s < SPB - 1) run |= prev[t + 1] != 0;
        if (!run) return;
    }

    __shared__ u64 sS[(RT + 2) * P];
    __shared__ u64 sF[(RT + 2) * P];
    const int tid = threadIdx.x;
    const int b  = t >> 6;
    const int y0 = s * RT;

    // load halo strip (rows y0-1 .. y0+RT)
    for (int k = tid; k < (RT + 2) * WPR; k += 256) {
        int r = k >> 4, w = k & (WPR - 1);
        int gy = y0 + r - 1;
        u64 f = 0ull, sv = 0ull;
        if ((unsigned)gy < (unsigned)H) {
            int o = (b * H + gy) * WPR + w;
            f = g_fill[o];
            sv = g_strong[o];
        }
        sF[r * P + w] = f;
        sS[r * P + w] = sv;
    }
    __syncthreads();

    const int w = tid & 15;
    const int r = (tid >> 4) + 1;               // rows 1..16, one per thread
    const u64 F = sF[r * P + w];
    u64 S = sS[r * P + w];

    int any = 0;
    for (;;) {
        int ch = 0;
        if (F != S) {
            u64 above = sS[(r - 1) * P + w];
            u64 below = sS[(r + 1) * P + w];
            u64 X = above | S | below;
            u64 XL = (w > 0)
                ? (sS[(r - 1) * P + w - 1] | sS[r * P + w - 1] | sS[(r + 1) * P + w - 1])
                : 0ull;
            u64 XR = (w < WPR - 1)
                ? (sS[(r - 1) * P + w + 1] | sS[r * P + w + 1] | sS[(r + 1) * P + w + 1])
                : 0ull;
            u64 d = X | (X << 1) | (XL >> 63) | (X >> 1) | (XR << 63);
            u64 ns = wflood(F, (F & d) | S);
            if (ns != S) {
                S = ns;
                sS[r * P + w] = ns;
                ch = 1;
            }
        }
        any |= ch;
        if (!__syncthreads_or(ch)) break;
    }

    if (__syncthreads_or(any)) {
        g_strong[(b * H + y0 + r - 1) * WPR + w] = S;
        if (tid == 0) g_dirty[pass][t] = 1;
    }
}

// =====================================================================
// Kernel C: edges = 1.0 where strong else 0.0
// =====================================================================
__global__ __launch_bounds__(256) void edges_final(float* __restrict__ e)
{
    int i = blockIdx.x * 256 + threadIdx.x;       // over NPIX/4
    unsigned wrd = ((const unsigned*)g_strong)[i >> 3];
    int sh = (i & 7) * 4;
    float4 f;
    f.x = (wrd >> (sh + 0)) & 1u ? 1.0f : 0.0f;
    f.y = (wrd >> (sh + 1)) & 1u ? 1.0f : 0.0f;
    f.z = (wrd >> (sh + 2)) & 1u ? 1.0f : 0.0f;
    f.w = (wrd >> (sh + 3)) & 1u ? 1.0f : 0.0f;
    ((float4*)e)[i] = f;
}

// =====================================================================
extern "C" void kernel_launch(void* const* d_in, const int* in_sizes, int n_in,
                              void* d_out, int out_size)
{
    (void)in_sizes; (void)n_in; (void)out_size;
    const float* x = (const float*)d_in[0];
    float* out = (float*)d_out;          // magnitude (4,1,1024,1024)
    float* edges = out + (size_t)NPIX;   // edges     (4,1,1024,1024)

    dim3 grid(32, 32, NB);
    canny_main<<<grid, 256>>>(x, out);

    for (int p = 0; p < NPASS; ++p)
        hyst_pass<<<HBLOCKS, 256>>>(p);

    edges_final<<<NPIX / 1024, 256>>>(edges);
}